// round 5
// baseline (speedup 1.0000x reference)
#include <cuda_runtime.h>
#include <cstdint>

// Problem constants
#define Bn     32
#define Tn     24
#define Sn     768
#define SPLIT  4               // CTAs per cluster (per batch)
#define KT     (Sn / SPLIT)    // 192 output columns per CTA
#define TXn    (KT / 4)        // 48 float4 column-groups
#define TYn    8               // i-stripe ways
#define NTHR   (TXn * TYn)     // 384 threads

__device__ __forceinline__ uint32_t smem_u32(const void* p) {
    return (uint32_t)__cvta_generic_to_shared(p);
}

__global__ void __cluster_dims__(SPLIT, 1, 1) __launch_bounds__(NTHR, 1)
scan_matvec_kernel(const float* __restrict__ inp,
                   const float* __restrict__ param,
                   float* __restrict__ out)
{
    // double-buffered full y vector for this batch
    __shared__ float ybuf[2][Sn];

    const int tid = threadIdx.x;
    const int ty  = tid & (TYn - 1);   // i-stripe   (8 consecutive lanes)
    const int tx  = tid >> 3;          // k-group    (float4)
    const int b   = blockIdx.x / SPLIT;

    uint32_t rank;
    asm("mov.u32 %0, %%cluster_ctarank;" : "=r"(rank));
    const int k0 = (int)rank * KT;

    // y0 = param + 1 (every CTA builds the full vector locally)
    for (int i = tid; i < Sn; i += NTHR)
        ybuf[0][i] = param[i] + 1.0f;

    // make sure all cluster CTAs are initialized before DSMEM traffic
    asm volatile("barrier.cluster.arrive.aligned;" ::: "memory");
    asm volatile("barrier.cluster.wait.aligned;"   ::: "memory");

    // this thread's fixed column offset within the matrix row
    const float* Mb = inp + (size_t)b * Tn * Sn * Sn + (size_t)(k0 + tx * 4);

    int p = 0;
    for (int t = 0; t < Tn; ++t) {
        const float* Mt = Mb + (size_t)t * Sn * Sn;
        const float* yp = ybuf[p];

        float ax = 0.f, ay = 0.f, az = 0.f, aw = 0.f;

        // strided i-reduction: thread handles i = ty, ty+8, ...
        const float* mp = Mt + (size_t)ty * Sn;
        #pragma unroll 8
        for (int i = ty; i < Sn; i += TYn) {
            float4 m = __ldcs(reinterpret_cast<const float4*>(mp));
            float  yv = yp[i];
            ax = fmaf(yv, m.x, ax);
            ay = fmaf(yv, m.y, ay);
            az = fmaf(yv, m.z, az);
            aw = fmaf(yv, m.w, aw);
            mp += (size_t)TYn * Sn;
        }

        // reduce across the 8-lane ty group (lanes are consecutive)
        #pragma unroll
        for (int off = 4; off; off >>= 1) {
            ax += __shfl_down_sync(0xffffffffu, ax, off);
            ay += __shfl_down_sync(0xffffffffu, ay, off);
            az += __shfl_down_sync(0xffffffffu, az, off);
            aw += __shfl_down_sync(0xffffffffu, aw, off);
        }

        if (ty == 0) {
            if (t == Tn - 1) {
                // final step: write PRE-ReLU y
                float4 r = make_float4(ax, ay, az, aw);
                *reinterpret_cast<float4*>(out + (size_t)b * Sn + k0 + tx * 4) = r;
            } else {
                // relu, then broadcast this CTA's slice into every cluster
                // CTA's next-parity buffer via DSMEM stores
                float rx = fmaxf(ax, 0.f);
                float ry = fmaxf(ay, 0.f);
                float rz = fmaxf(az, 0.f);
                float rw = fmaxf(aw, 0.f);
                uint32_t la = smem_u32(&ybuf[p ^ 1][k0 + tx * 4]);
                #pragma unroll
                for (int rr = 0; rr < SPLIT; ++rr) {
                    uint32_t ra;
                    asm("mapa.shared::cluster.u32 %0, %1, %2;"
                        : "=r"(ra) : "r"(la), "r"(rr));
                    asm volatile("st.shared::cluster.f32 [%0],    %1;" :: "r"(ra), "f"(rx) : "memory");
                    asm volatile("st.shared::cluster.f32 [%0+4],  %1;" :: "r"(ra), "f"(ry) : "memory");
                    asm volatile("st.shared::cluster.f32 [%0+8],  %1;" :: "r"(ra), "f"(rz) : "memory");
                    asm volatile("st.shared::cluster.f32 [%0+12], %1;" :: "r"(ra), "f"(rw) : "memory");
                }
            }
        }

        if (t < Tn - 1) {
            // one cluster barrier per step: orders the DSMEM stores above
            // (release on arrive) before anyone reads ybuf[p^1] (acquire on wait)
            asm volatile("barrier.cluster.arrive.aligned;" ::: "memory");
            asm volatile("barrier.cluster.wait.aligned;"   ::: "memory");
            p ^= 1;
        }
    }
}

extern "C" void kernel_launch(void* const* d_in, const int* in_sizes, int n_in,
                              void* d_out, int out_size)
{
    const float* inp   = (const float*)d_in[0];   // [32, 24, 768, 768] f32
    const float* param = (const float*)d_in[1];   // [768] f32
    float* out = (float*)d_out;                   // [32, 768] f32

    (void)in_sizes; (void)n_in; (void)out_size;

    scan_matvec_kernel<<<Bn * SPLIT, NTHR>>>(inp, param, out);
}

// round 7
// speedup vs baseline: 1.9440x; 1.9440x over previous
#include <cuda_runtime.h>
#include <cstdint>

// Problem constants
#define Bn     32
#define Tn     24
#define Sn     768
#define SPLIT  4               // CTAs per cluster (per batch)
#define KT     (Sn / SPLIT)    // 192 output columns per CTA
#define CT     3               // column tiles of 64 floats (16 float4) per CTA
#define STR    8               // row stripes
#define NW     (CT * STR)      // 24 warps
#define NTHR   (NW * 32)       // 768 threads
#define NJ     (Sn / (2*STR)) // 48 row-pair iterations per warp
#define JG     8               // unroll / MLP depth
#define NG     (NJ / JG)       // 6 groups

__device__ __forceinline__ uint32_t smem_u32(const void* p) {
    return (uint32_t)__cvta_generic_to_shared(p);
}

__global__ void __cluster_dims__(SPLIT, 1, 1) __launch_bounds__(NTHR, 1)
scan_matvec_kernel(const float* __restrict__ inp,
                   const float* __restrict__ param,
                   float* __restrict__ out)
{
    // double-buffered full y vector for this batch
    __shared__ float  ybuf[2][Sn];
    __shared__ float4 red[STR][KT / 4];   // [8][48] stripe partials

    const int tid  = threadIdx.x;
    const int w    = tid >> 5;
    const int lane = tid & 31;
    const int c    = w % CT;          // column tile (64 floats)
    const int s    = w / CT;          // row stripe
    const int half = lane >> 4;       // row within pair
    const int g    = lane & 15;       // float4 group within tile
    const int b    = blockIdx.x / SPLIT;

    uint32_t rank;
    asm("mov.u32 %0, %%cluster_ctarank;" : "=r"(rank));
    const int k0 = (int)rank * KT;

    // y0 = param + 1 (768 threads, one element each)
    ybuf[0][tid] = param[tid] + 1.0f;
    __syncthreads();

    // warp-contiguous load base: lanes 0-15 cover 256B of row i0,
    // lanes 16-31 cover 256B of row i0+1  -> 4 lines per warp-LDG
    const int i0 = 2 * s + half;
    const float* Mth = inp + (size_t)b * Tn * Sn * Sn
                           + (size_t)i0 * Sn + (k0 + c * 64 + g * 4);

    int p = 0;
    for (int t = 0; t < Tn; ++t) {
        const float* mp = Mth + (size_t)t * Sn * Sn;
        const float* yp = ybuf[p];

        float ax = 0.f, ay = 0.f, az = 0.f, aw = 0.f;
        int yi = i0;

        for (int jg = 0; jg < NG; ++jg) {
            float4 m[JG];
            float  yv[JG];
            // front-batched loads: 8 independent LDG.128 in flight
            #pragma unroll
            for (int u = 0; u < JG; ++u) {
                m[u]  = __ldcs(reinterpret_cast<const float4*>(
                            mp + (size_t)u * (2 * STR) * Sn));
                yv[u] = yp[yi + u * (2 * STR)];
            }
            mp += (size_t)JG * (2 * STR) * Sn;
            yi += JG * (2 * STR);
            #pragma unroll
            for (int u = 0; u < JG; ++u) {
                ax = fmaf(yv[u], m[u].x, ax);
                ay = fmaf(yv[u], m[u].y, ay);
                az = fmaf(yv[u], m[u].z, az);
                aw = fmaf(yv[u], m[u].w, aw);
            }
        }

        // combine the two row-halves (same columns) within the warp
        ax += __shfl_down_sync(0xffffffffu, ax, 16);
        ay += __shfl_down_sync(0xffffffffu, ay, 16);
        az += __shfl_down_sync(0xffffffffu, az, 16);
        aw += __shfl_down_sync(0xffffffffu, aw, 16);

        if (half == 0)
            red[s][c * 16 + g] = make_float4(ax, ay, az, aw);
        __syncthreads();

        // 48 threads: reduce 8 stripes, then relu + cluster broadcast
        if (tid < KT / 4) {
            float4 r = red[0][tid];
            #pragma unroll
            for (int ss = 1; ss < STR; ++ss) {
                float4 q = red[ss][tid];
                r.x += q.x; r.y += q.y; r.z += q.z; r.w += q.w;
            }
            if (t == Tn - 1) {
                // final step: PRE-ReLU y
                *reinterpret_cast<float4*>(out + (size_t)b * Sn + k0 + tid * 4) = r;
            } else {
                r.x = fmaxf(r.x, 0.f); r.y = fmaxf(r.y, 0.f);
                r.z = fmaxf(r.z, 0.f); r.w = fmaxf(r.w, 0.f);
                uint32_t la = smem_u32(&ybuf[p ^ 1][k0 + tid * 4]);
                #pragma unroll
                for (int rr = 0; rr < SPLIT; ++rr) {
                    uint32_t ra;
                    asm("mapa.shared::cluster.u32 %0, %1, %2;"
                        : "=r"(ra) : "r"(la), "r"(rr));
                    asm volatile("st.shared::cluster.v4.f32 [%0], {%1,%2,%3,%4};"
                                 :: "r"(ra), "f"(r.x), "f"(r.y), "f"(r.z), "f"(r.w)
                                 : "memory");
                }
            }
        }

        if (t < Tn - 1) {
            // one cluster barrier per step: release DSMEM y stores,
            // acquire before anyone reads ybuf[p^1]
            asm volatile("barrier.cluster.arrive.aligned;" ::: "memory");
            asm volatile("barrier.cluster.wait.aligned;"   ::: "memory");
            p ^= 1;
        }
    }
}

extern "C" void kernel_launch(void* const* d_in, const int* in_sizes, int n_in,
                              void* d_out, int out_size)
{
    const float* inp   = (const float*)d_in[0];   // [32, 24, 768, 768] f32
    const float* param = (const float*)d_in[1];   // [768] f32
    float* out = (float*)d_out;                   // [32, 768] f32

    (void)in_sizes; (void)n_in; (void)out_size;

    scan_matvec_kernel<<<Bn * SPLIT, NTHR>>>(inp, param, out);
}